// round 1
// baseline (speedup 1.0000x reference)
#include <cuda_runtime.h>

// ---------------------------------------------------------------------------
// GCN link prediction:
//   h1 = relu(GCNConv(x, E, W1, b1));  z = GCNConv(h1, E, W2, b2)
//   logits[e] = dot(z[a_e], z[b_e]) over concatenated pos/neg edges
//
// GCNConv rewritten: hs = (x@W) * dinv (per-row scale), acc[c] = hs[c] (self
// loop) + sum over incoming edges of hs[row], out = dinv[c]*acc[c] + b.
// ---------------------------------------------------------------------------

#define N_NODES 50000
#define E_TRAIN 1600000
#define EP      200000
#define EN      200000
#define F_IN    50
#define HID     50
#define DOUT    64
#define PAD     64   // padded row width (256B rows, float4-friendly)

__device__ __align__(256) float g_bufA[N_NODES * PAD]; // hs (gather source)
__device__ __align__(256) float g_bufB[N_NODES * PAD]; // acc (scatter target)
__device__ __align__(256) float g_bufC[N_NODES * PAD]; // layer output / z
__device__ int   g_deg[N_NODES];
__device__ float g_dinv[N_NODES];

// ---- degree / normalization -----------------------------------------------
__global__ void k_init_deg() {
    int i = blockIdx.x * blockDim.x + threadIdx.x;
    if (i < N_NODES) g_deg[i] = 1;   // self loop
}

__global__ void k_count(const int* __restrict__ dst) {
    int e = blockIdx.x * blockDim.x + threadIdx.x;  // grid exact: 1.6M/256
    atomicAdd(&g_deg[dst[e]], 1);
}

__global__ void k_dinv() {
    int i = blockIdx.x * blockDim.x + threadIdx.x;
    if (i < N_NODES) g_dinv[i] = rsqrtf((float)g_deg[i]);
}

// ---- GEMM 1: bufA = bufB = dinv[i] * (x @ W1), padded to 64 cols ----------
__global__ __launch_bounds__(512) void k_gemm1(const float* __restrict__ x,
                                               const float* __restrict__ W1) {
    __shared__ float ws[F_IN * HID];    // 50x50
    __shared__ float xs[8][F_IN];
    int tid = threadIdx.x;
    int nodeBase = blockIdx.x * 8;      // 6250 blocks, always full
    for (int t = tid; t < F_IN * HID; t += 512) ws[t] = W1[t];
    for (int t = tid; t < 8 * F_IN; t += 512) {
        int n = t / F_IN, k = t % F_IN;
        xs[n][k] = x[(nodeBase + n) * F_IN + k];
    }
    __syncthreads();
    int j = tid & 63, n = tid >> 6;
    int node = nodeBase + n;
    float acc = 0.f;
    if (j < HID) {
#pragma unroll
        for (int k = 0; k < F_IN; k++) acc += xs[n][k] * ws[k * HID + j];
        acc *= g_dinv[node];
    }
    g_bufA[node * PAD + j] = acc;
    g_bufB[node * PAD + j] = acc;
}

// ---- GEMM 2: bufA = bufB = dinv[i] * (bufC @ W2) --------------------------
__global__ __launch_bounds__(512) void k_gemm2(const float* __restrict__ W2) {
    __shared__ float ws[HID * DOUT];    // 50x64
    __shared__ float xs[8][HID];
    int tid = threadIdx.x;
    int nodeBase = blockIdx.x * 8;
    for (int t = tid; t < HID * DOUT; t += 512) ws[t] = W2[t];
    for (int t = tid; t < 8 * HID; t += 512) {
        int n = t / HID, k = t % HID;
        xs[n][k] = g_bufC[(nodeBase + n) * PAD + k];
    }
    __syncthreads();
    int j = tid & 63, n = tid >> 6;
    int node = nodeBase + n;
    float acc = 0.f;
#pragma unroll
    for (int k = 0; k < HID; k++) acc += xs[n][k] * ws[k * DOUT + j];
    acc *= g_dinv[node];
    g_bufA[node * PAD + j] = acc;
    g_bufB[node * PAD + j] = acc;
}

// ---- edge scatter: bufB[dst] += bufA[src], CH float4 chunks per edge ------
template <int CH>
__global__ void k_scatter(const int* __restrict__ src,
                          const int* __restrict__ dst) {
    int gt = blockIdx.x * 256 + threadIdx.x;  // 16 lanes per edge
    int e = gt >> 4;
    int j = gt & 15;
    if (j >= CH) return;
    int r = src[e];
    int c = dst[e];
    float4 v = __ldg((const float4*)(g_bufA + r * PAD) + j);
    float* pc = g_bufB + c * PAD + j * 4;
    asm volatile("red.global.add.v4.f32 [%0], {%1,%2,%3,%4};"
                 :: "l"(pc), "f"(v.x), "f"(v.y), "f"(v.z), "f"(v.w)
                 : "memory");
}

// ---- epilogues ------------------------------------------------------------
__global__ void k_post1(const float* __restrict__ b1) {
    int t = blockIdx.x * 256 + threadIdx.x;  // 3.2M threads exact
    int i = t >> 6, j = t & 63;
    float v = 0.f;
    if (j < HID) v = fmaxf(g_dinv[i] * g_bufB[t] + b1[j], 0.f);
    g_bufC[t] = v;
}

__global__ void k_post2(const float* __restrict__ b2) {
    int t = blockIdx.x * 256 + threadIdx.x;
    int i = t >> 6, j = t & 63;
    g_bufC[t] = g_dinv[i] * g_bufB[t] + b2[j];
}

// ---- decode: logits[e] = dot64(z[a], z[b]) --------------------------------
__global__ void k_decode(const int* __restrict__ pos,
                         const int* __restrict__ neg,
                         float* __restrict__ out) {
    int gt = blockIdx.x * 256 + threadIdx.x;  // 6.4M threads exact
    int e = gt >> 4;
    int j = gt & 15;
    int a, b;
    if (e < EP) { a = pos[e];       b = pos[EP + e]; }
    else        { int e2 = e - EP; a = neg[e2]; b = neg[EN + e2]; }
    float4 za = __ldg((const float4*)(g_bufC + a * PAD) + j);
    float4 zb = __ldg((const float4*)(g_bufC + b * PAD) + j);
    float s = za.x * zb.x + za.y * zb.y + za.z * zb.z + za.w * zb.w;
#pragma unroll
    for (int o = 8; o; o >>= 1) s += __shfl_xor_sync(0xffffffffu, s, o);
    if (j == 0) out[e] = s;
}

// ---------------------------------------------------------------------------
extern "C" void kernel_launch(void* const* d_in, const int* in_sizes, int n_in,
                              void* d_out, int out_size) {
    const float* x   = (const float*)d_in[0];
    const int*   tr  = (const int*)d_in[1];   // [2, E_TRAIN]: row0=src, row1=dst
    const int*   pos = (const int*)d_in[2];   // [2, EP]
    const int*   neg = (const int*)d_in[3];   // [2, EN]
    const float* W1  = (const float*)d_in[4];
    const float* b1  = (const float*)d_in[5];
    const float* W2  = (const float*)d_in[6];
    const float* b2  = (const float*)d_in[7];
    float* out = (float*)d_out;

    const int* src = tr;
    const int* dst = tr + E_TRAIN;

    k_init_deg<<<(N_NODES + 255) / 256, 256>>>();
    k_count<<<E_TRAIN / 256, 256>>>(dst);
    k_dinv<<<(N_NODES + 255) / 256, 256>>>();

    k_gemm1<<<N_NODES / 8, 512>>>(x, W1);
    k_scatter<13><<<E_TRAIN * 16 / 256, 256>>>(src, dst);
    k_post1<<<N_NODES * PAD / 256, 256>>>(b1);

    k_gemm2<<<N_NODES / 8, 512>>>(W2);
    k_scatter<16><<<E_TRAIN * 16 / 256, 256>>>(src, dst);
    k_post2<<<N_NODES * PAD / 256, 256>>>(b2);

    k_decode<<<(EP + EN) * 16 / 256, 256>>>(pos, neg, out);
}

// round 4
// speedup vs baseline: 1.0467x; 1.0467x over previous
#include <cuda_runtime.h>

// ---------------------------------------------------------------------------
// GCN link prediction, CSR-gather formulation (no float atomics):
//   hs = (x@W)*dinv  ->  acc[c] = hs[c] + sum_{e: dst=c} hs[src_e]
//   out[c] = dinv[c]*acc[c] + b   (relu for layer 1)
// CSR over dst built once per call (count -> scan -> place), reused by both
// layers. Aggregation: 1 warp/node, half-warp per edge, float4 lanes.
// NOTE: device globals are only referenced from device code (never passed as
// kernel args from host — that was the round-2 crash).
// ---------------------------------------------------------------------------

#define N_NODES 50000
#define E_TRAIN 1600000
#define EP      200000
#define EN      200000
#define F_IN    50
#define HID     50
#define DOUT    64
#define PAD     64

__device__ __align__(256) float g_bufA[N_NODES * PAD]; // hs (gather source)
__device__ __align__(256) float g_bufC[N_NODES * PAD]; // layer output / z
__device__ int   g_deg[N_NODES];
__device__ int   g_rowptr[N_NODES + 1];
__device__ int   g_cursor[N_NODES];
__device__ int   g_esrc[E_TRAIN];
__device__ float g_dinv[N_NODES];

// ---- degree -----------------------------------------------------------------
__global__ void k_zero() {
    int i = blockIdx.x * blockDim.x + threadIdx.x;
    if (i < N_NODES) g_deg[i] = 0;
}

__global__ void k_count(const int* __restrict__ dst) {
    int e = blockIdx.x * 256 + threadIdx.x;   // grid exact
    atomicAdd(&g_deg[dst[e]], 1);
}

// ---- single-block exclusive scan -> rowptr/cursor/dinv ----------------------
#define SCAN_T 1024
#define CHUNK  49     // 1024*49 = 50176 >= 50000

__global__ __launch_bounds__(SCAN_T) void k_scan() {
    __shared__ int part[SCAN_T];
    int t = threadIdx.x;
    int base = t * CHUNK;
    int s = 0;
    for (int i = 0; i < CHUNK; i++) {
        int idx = base + i;
        if (idx < N_NODES) s += g_deg[idx];
    }
    part[t] = s;
    __syncthreads();
    for (int off = 1; off < SCAN_T; off <<= 1) {
        int v = (t >= off) ? part[t - off] : 0;
        __syncthreads();
        part[t] += v;
        __syncthreads();
    }
    int run = (t > 0) ? part[t - 1] : 0;
    for (int i = 0; i < CHUNK; i++) {
        int idx = base + i;
        if (idx < N_NODES) {
            int d = g_deg[idx];
            g_rowptr[idx] = run;
            g_cursor[idx] = run;
            g_dinv[idx]   = rsqrtf((float)(d + 1));   // +1 self loop
            run += d;
        }
    }
    if (t == SCAN_T - 1) g_rowptr[N_NODES] = run;
}

__global__ void k_place(const int* __restrict__ src, const int* __restrict__ dst) {
    int e = blockIdx.x * 256 + threadIdx.x;
    int p = atomicAdd(&g_cursor[dst[e]], 1);
    g_esrc[p] = src[e];
}

// ---- GEMM 1: bufA = dinv[i] * (x @ W1), W padded to 64 cols -----------------
__global__ __launch_bounds__(256) void k_gemm1(const float* __restrict__ x,
                                               const float* __restrict__ W1) {
    __shared__ float ws[F_IN][64];
    __shared__ float xs[16][F_IN + 2];
    int tid = threadIdx.x;
    int nodeBase = blockIdx.x * 16;                 // 3125 blocks, always full
    for (int t = tid; t < F_IN * 64; t += 256) {
        int k = t >> 6, j = t & 63;
        ws[k][j] = (j < HID) ? W1[k * HID + j] : 0.f;
    }
    for (int t = tid; t < 16 * F_IN; t += 256) {
        int n = t / F_IN, k = t % F_IN;
        xs[n][k] = x[(nodeBase + n) * F_IN + k];
    }
    __syncthreads();
    int n = tid >> 4, jq = tid & 15;
    int node = nodeBase + n;
    float4 acc = make_float4(0.f, 0.f, 0.f, 0.f);
#pragma unroll
    for (int k = 0; k < F_IN; k++) {
        float xv = xs[n][k];
        float4 w = *(const float4*)&ws[k][jq * 4];
        acc.x = fmaf(xv, w.x, acc.x);
        acc.y = fmaf(xv, w.y, acc.y);
        acc.z = fmaf(xv, w.z, acc.z);
        acc.w = fmaf(xv, w.w, acc.w);
    }
    float di = g_dinv[node];
    acc.x *= di; acc.y *= di; acc.z *= di; acc.w *= di;
    *(float4*)&g_bufA[node * PAD + jq * 4] = acc;
}

// ---- GEMM 2: bufA = dinv[i] * (bufC @ W2) -----------------------------------
__global__ __launch_bounds__(256) void k_gemm2(const float* __restrict__ W2) {
    __shared__ float ws[HID][64];
    __shared__ float xs[16][HID + 2];
    int tid = threadIdx.x;
    int nodeBase = blockIdx.x * 16;
    for (int t = tid; t < HID * 64; t += 256) {
        int k = t >> 6, j = t & 63;
        ws[k][j] = W2[k * DOUT + j];
    }
    for (int t = tid; t < 16 * HID; t += 256) {
        int n = t / HID, k = t % HID;
        xs[n][k] = g_bufC[(nodeBase + n) * PAD + k];
    }
    __syncthreads();
    int n = tid >> 4, jq = tid & 15;
    int node = nodeBase + n;
    float4 acc = make_float4(0.f, 0.f, 0.f, 0.f);
#pragma unroll
    for (int k = 0; k < HID; k++) {
        float xv = xs[n][k];
        float4 w = *(const float4*)&ws[k][jq * 4];
        acc.x = fmaf(xv, w.x, acc.x);
        acc.y = fmaf(xv, w.y, acc.y);
        acc.z = fmaf(xv, w.z, acc.z);
        acc.w = fmaf(xv, w.w, acc.w);
    }
    float di = g_dinv[node];
    acc.x *= di; acc.y *= di; acc.z *= di; acc.w *= di;
    *(float4*)&g_bufA[node * PAD + jq * 4] = acc;
}

// ---- CSR aggregation + fused epilogue ---------------------------------------
// One warp per node. Half-warp h processes edges rp+h, rp+h+2, ...
// Lane q (0..15) owns float4 chunk q of the 64-col row.
// Reads g_bufA, writes g_bufC (device globals referenced in device code only).
template <int CH, int NB, bool RELU>
__global__ __launch_bounds__(256) void k_agg(const float* __restrict__ bias) {
    const float* __restrict__ in   = g_bufA;
    float* __restrict__       outb = g_bufC;
    int node = (blockIdx.x * 256 + threadIdx.x) >> 5;   // grid exact: 6250 blocks
    int lane = threadIdx.x & 31;
    int half = lane >> 4, q = lane & 15;
    int rp = g_rowptr[node], re = g_rowptr[node + 1];
    const bool act = (CH == 16) || (q < CH);
    float4 acc = make_float4(0.f, 0.f, 0.f, 0.f);
    if (half == 0 && act) acc = *(const float4*)(in + node * PAD + q * 4); // self loop
    for (int e = rp + half; e < re; e += 2) {
        int s = g_esrc[e];
        if (act) {
            float4 v = __ldg((const float4*)(in + s * PAD) + q);
            acc.x += v.x; acc.y += v.y; acc.z += v.z; acc.w += v.w;
        }
    }
    acc.x += __shfl_xor_sync(0xffffffffu, acc.x, 16);
    acc.y += __shfl_xor_sync(0xffffffffu, acc.y, 16);
    acc.z += __shfl_xor_sync(0xffffffffu, acc.z, 16);
    acc.w += __shfl_xor_sync(0xffffffffu, acc.w, 16);
    if (half == 0 && act) {
        float di = g_dinv[node];
        int j = q * 4;
        float b0 = (j + 0 < NB) ? __ldg(bias + j + 0) : 0.f;
        float b1 = (j + 1 < NB) ? __ldg(bias + j + 1) : 0.f;
        float b2 = (j + 2 < NB) ? __ldg(bias + j + 2) : 0.f;
        float b3 = (j + 3 < NB) ? __ldg(bias + j + 3) : 0.f;
        float4 r;
        r.x = fmaf(di, acc.x, b0);
        r.y = fmaf(di, acc.y, b1);
        r.z = fmaf(di, acc.z, b2);
        r.w = fmaf(di, acc.w, b3);
        if (RELU) {
            r.x = fmaxf(r.x, 0.f); r.y = fmaxf(r.y, 0.f);
            r.z = fmaxf(r.z, 0.f); r.w = fmaxf(r.w, 0.f);
        }
        *(float4*)(outb + node * PAD + j) = r;
    }
}

// ---- decode: logits[e] = dot64(z[a], z[b]) ----------------------------------
__global__ void k_decode(const int* __restrict__ pos,
                         const int* __restrict__ neg,
                         float* __restrict__ out) {
    int gt = blockIdx.x * 256 + threadIdx.x;
    int e = gt >> 4;
    int j = gt & 15;
    int a, b;
    if (e < EP) { a = pos[e];        b = pos[EP + e]; }
    else        { int e2 = e - EP;  a = neg[e2];     b = neg[EN + e2]; }
    float4 za = __ldg((const float4*)(g_bufC + a * PAD) + j);
    float4 zb = __ldg((const float4*)(g_bufC + b * PAD) + j);
    float s = za.x * zb.x + za.y * zb.y + za.z * zb.z + za.w * zb.w;
#pragma unroll
    for (int o = 8; o; o >>= 1) s += __shfl_xor_sync(0xffffffffu, s, o);
    if (j == 0) out[e] = s;
}

// ---------------------------------------------------------------------------
extern "C" void kernel_launch(void* const* d_in, const int* in_sizes, int n_in,
                              void* d_out, int out_size) {
    const float* x   = (const float*)d_in[0];
    const int*   tr  = (const int*)d_in[1];
    const int*   pos = (const int*)d_in[2];
    const int*   neg = (const int*)d_in[3];
    const float* x_unused = x; (void)x_unused;
    const float* W1  = (const float*)d_in[4];
    const float* b1  = (const float*)d_in[5];
    const float* W2  = (const float*)d_in[6];
    const float* b2  = (const float*)d_in[7];
    float* out = (float*)d_out;

    const int* src = tr;
    const int* dst = tr + E_TRAIN;

    // CSR build (reused by both layers)
    k_zero<<<(N_NODES + 255) / 256, 256>>>();
    k_count<<<E_TRAIN / 256, 256>>>(dst);
    k_scan<<<1, SCAN_T>>>();
    k_place<<<E_TRAIN / 256, 256>>>(src, dst);

    // layer 1
    k_gemm1<<<N_NODES / 16, 256>>>(x, W1);
    k_agg<13, HID, true><<<N_NODES * 32 / 256, 256>>>(b1);

    // layer 2
    k_gemm2<<<N_NODES / 16, 256>>>(W2);
    k_agg<16, DOUT, false><<<N_NODES * 32 / 256, 256>>>(b2);

    // decode
    k_decode<<<(EP + EN) * 16 / 256, 256>>>(pos, neg, out);
}

// round 5
// speedup vs baseline: 1.0742x; 1.0262x over previous
#include <cuda_runtime.h>
#include <cuda_fp16.h>

// ---------------------------------------------------------------------------
// GCN link prediction, CSR-gather formulation:
//   hs = (x@W)*dinv (stored fp16) -> acc[c] = hs[c] + sum_{dst=c} hs[src]
//   out[c] = dinv[c]*acc[c] + b  (relu layer 1), fp32
// Gather-source rows are fp16 (128B/row) since they are read ~32x each;
// accumulation and all other buffers stay fp32.
// ---------------------------------------------------------------------------

#define N_NODES 50000
#define E_TRAIN 1600000
#define EP      200000
#define EN      200000
#define F_IN    50
#define HID     50
#define DOUT    64
#define PAD     64

__device__ __align__(256) __half g_bufA[N_NODES * PAD]; // hs fp16 (gather src)
__device__ __align__(256) float  g_bufC[N_NODES * PAD]; // layer output / z
__device__ int   g_deg[N_NODES];
__device__ int   g_rowptr[N_NODES + 1];
__device__ int   g_cursor[N_NODES];
__device__ int   g_esrc[E_TRAIN];
__device__ float g_dinv[N_NODES];

// ---- degree (4 edges/thread for MLP) ----------------------------------------
__global__ void k_zero() {
    int i = blockIdx.x * blockDim.x + threadIdx.x;
    if (i < N_NODES) g_deg[i] = 0;
}

__global__ void k_count(const int* __restrict__ dst) {
    int t = blockIdx.x * 256 + threadIdx.x;
    if (t < E_TRAIN / 4) {
        int4 d = __ldg((const int4*)dst + t);
        atomicAdd(&g_deg[d.x], 1);
        atomicAdd(&g_deg[d.y], 1);
        atomicAdd(&g_deg[d.z], 1);
        atomicAdd(&g_deg[d.w], 1);
    }
}

// ---- single-block exclusive scan -> rowptr/cursor/dinv ----------------------
#define SCAN_T 1024
#define CHUNK  49     // 1024*49 = 50176 >= 50000

__global__ __launch_bounds__(SCAN_T) void k_scan() {
    __shared__ int part[SCAN_T];
    int t = threadIdx.x;
    int base = t * CHUNK;
    int s = 0;
#pragma unroll 7
    for (int i = 0; i < CHUNK; i++) {
        int idx = base + i;
        if (idx < N_NODES) s += __ldg(g_deg + idx);
    }
    part[t] = s;
    __syncthreads();
    for (int off = 1; off < SCAN_T; off <<= 1) {
        int v = (t >= off) ? part[t - off] : 0;
        __syncthreads();
        part[t] += v;
        __syncthreads();
    }
    int run = (t > 0) ? part[t - 1] : 0;
    for (int i = 0; i < CHUNK; i++) {
        int idx = base + i;
        if (idx < N_NODES) {
            int d = g_deg[idx];
            g_rowptr[idx] = run;
            g_cursor[idx] = run;
            g_dinv[idx]   = rsqrtf((float)(d + 1));   // +1 self loop
            run += d;
        }
    }
    if (t == SCAN_T - 1) g_rowptr[N_NODES] = run;
}

__global__ void k_place(const int* __restrict__ src, const int* __restrict__ dst) {
    int t = blockIdx.x * 256 + threadIdx.x;
    if (t < E_TRAIN / 4) {
        int4 s = __ldg((const int4*)src + t);
        int4 d = __ldg((const int4*)dst + t);
        int p0 = atomicAdd(&g_cursor[d.x], 1);
        int p1 = atomicAdd(&g_cursor[d.y], 1);
        int p2 = atomicAdd(&g_cursor[d.z], 1);
        int p3 = atomicAdd(&g_cursor[d.w], 1);
        g_esrc[p0] = s.x;
        g_esrc[p1] = s.y;
        g_esrc[p2] = s.z;
        g_esrc[p3] = s.w;
    }
}

// ---- GEMM 1: bufA = fp16( dinv[i] * (x @ W1) ), W padded to 64 cols --------
__global__ __launch_bounds__(256) void k_gemm1(const float* __restrict__ x,
                                               const float* __restrict__ W1) {
    __shared__ float ws[F_IN][64];
    __shared__ float xs[16][F_IN + 2];
    int tid = threadIdx.x;
    int nodeBase = blockIdx.x * 16;                 // 3125 blocks, always full
    for (int t = tid; t < F_IN * 64; t += 256) {
        int k = t >> 6, j = t & 63;
        ws[k][j] = (j < HID) ? W1[k * HID + j] : 0.f;
    }
    for (int t = tid; t < 16 * F_IN; t += 256) {
        int n = t / F_IN, k = t % F_IN;
        xs[n][k] = x[(nodeBase + n) * F_IN + k];
    }
    __syncthreads();
    int n = tid >> 4, jq = tid & 15;
    int node = nodeBase + n;
    float4 acc = make_float4(0.f, 0.f, 0.f, 0.f);
#pragma unroll
    for (int k = 0; k < F_IN; k++) {
        float xv = xs[n][k];
        float4 w = *(const float4*)&ws[k][jq * 4];
        acc.x = fmaf(xv, w.x, acc.x);
        acc.y = fmaf(xv, w.y, acc.y);
        acc.z = fmaf(xv, w.z, acc.z);
        acc.w = fmaf(xv, w.w, acc.w);
    }
    float di = g_dinv[node];
    __half2 p0 = __floats2half2_rn(acc.x * di, acc.y * di);
    __half2 p1 = __floats2half2_rn(acc.z * di, acc.w * di);
    uint2 st;
    st.x = *(unsigned*)&p0;
    st.y = *(unsigned*)&p1;
    *(uint2*)&g_bufA[node * PAD + jq * 4] = st;
}

// ---- GEMM 2: bufA = fp16( dinv[i] * (bufC @ W2) ) ---------------------------
__global__ __launch_bounds__(256) void k_gemm2(const float* __restrict__ W2) {
    __shared__ float ws[HID][64];
    __shared__ float xs[16][HID + 2];
    int tid = threadIdx.x;
    int nodeBase = blockIdx.x * 16;
    for (int t = tid; t < HID * 64; t += 256) {
        int k = t >> 6, j = t & 63;
        ws[k][j] = W2[k * DOUT + j];
    }
    for (int t = tid; t < 16 * HID; t += 256) {
        int n = t / HID, k = t % HID;
        xs[n][k] = g_bufC[(nodeBase + n) * PAD + k];
    }
    __syncthreads();
    int n = tid >> 4, jq = tid & 15;
    int node = nodeBase + n;
    float4 acc = make_float4(0.f, 0.f, 0.f, 0.f);
#pragma unroll
    for (int k = 0; k < HID; k++) {
        float xv = xs[n][k];
        float4 w = *(const float4*)&ws[k][jq * 4];
        acc.x = fmaf(xv, w.x, acc.x);
        acc.y = fmaf(xv, w.y, acc.y);
        acc.z = fmaf(xv, w.z, acc.z);
        acc.w = fmaf(xv, w.w, acc.w);
    }
    float di = g_dinv[node];
    __half2 p0 = __floats2half2_rn(acc.x * di, acc.y * di);
    __half2 p1 = __floats2half2_rn(acc.z * di, acc.w * di);
    uint2 st;
    st.x = *(unsigned*)&p0;
    st.y = *(unsigned*)&p1;
    *(uint2*)&g_bufA[node * PAD + jq * 4] = st;
}

// ---- CSR aggregation + fused epilogue ---------------------------------------
// One warp per node. 4 edge-groups of 8 lanes; lane q owns 16B chunk q
// (8 halves) of the 128B fp16 row. fp32 accumulation, 2x unrolled loop.
template <int NB, bool RELU>
__global__ __launch_bounds__(256) void k_agg(const float* __restrict__ bias) {
    int node = (blockIdx.x * 256 + threadIdx.x) >> 5;   // 6250 blocks exact
    int lane = threadIdx.x & 31;
    int g = lane >> 3, q = lane & 7;
    int rp = g_rowptr[node], re = g_rowptr[node + 1];
    float a0 = 0.f, a1 = 0.f, a2 = 0.f, a3 = 0.f;
    float a4 = 0.f, a5 = 0.f, a6 = 0.f, a7 = 0.f;
    const uint4* rows = (const uint4*)g_bufA;           // 8 uint4 per row

#define ACCUM(U) do {                                                   \
        __half2* hp = (__half2*)&(U);                                   \
        float2 f0 = __half22float2(hp[0]);                              \
        float2 f1 = __half22float2(hp[1]);                              \
        float2 f2 = __half22float2(hp[2]);                              \
        float2 f3 = __half22float2(hp[3]);                              \
        a0 += f0.x; a1 += f0.y; a2 += f1.x; a3 += f1.y;                 \
        a4 += f2.x; a5 += f2.y; a6 += f3.x; a7 += f3.y;                 \
    } while (0)

    if (g == 0) {                                       // self loop
        uint4 u = __ldg(rows + node * 8 + q);
        ACCUM(u);
    }
    int e = rp + g;
    for (; e + 4 < re; e += 8) {
        int s0 = __ldg(g_esrc + e);
        int s1 = __ldg(g_esrc + e + 4);
        uint4 u0 = __ldg(rows + s0 * 8 + q);
        uint4 u1 = __ldg(rows + s1 * 8 + q);
        ACCUM(u0);
        ACCUM(u1);
    }
    if (e < re) {
        int s0 = __ldg(g_esrc + e);
        uint4 u0 = __ldg(rows + s0 * 8 + q);
        ACCUM(u0);
    }
#undef ACCUM

#define RED(off) do {                                                   \
        a0 += __shfl_xor_sync(0xffffffffu, a0, off);                    \
        a1 += __shfl_xor_sync(0xffffffffu, a1, off);                    \
        a2 += __shfl_xor_sync(0xffffffffu, a2, off);                    \
        a3 += __shfl_xor_sync(0xffffffffu, a3, off);                    \
        a4 += __shfl_xor_sync(0xffffffffu, a4, off);                    \
        a5 += __shfl_xor_sync(0xffffffffu, a5, off);                    \
        a6 += __shfl_xor_sync(0xffffffffu, a6, off);                    \
        a7 += __shfl_xor_sync(0xffffffffu, a7, off);                    \
    } while (0)
    RED(8);
    RED(16);
#undef RED

    if (g == 0) {
        float di = g_dinv[node];
        int j0 = q * 8;
        float acc[8] = {a0, a1, a2, a3, a4, a5, a6, a7};
        float4 r0, r1;
        float* rr = &r0.x;
#pragma unroll
        for (int i = 0; i < 8; i++) {
            int j = j0 + i;
            float bv = (j < NB) ? __ldg(bias + j) : 0.f;
            float v = fmaf(di, acc[i], bv);
            if (RELU) v = fmaxf(v, 0.f);
            if (i < 4) (&r0.x)[i] = v; else (&r1.x)[i - 4] = v;
        }
        (void)rr;
        *(float4*)(g_bufC + node * PAD + j0)     = r0;
        *(float4*)(g_bufC + node * PAD + j0 + 4) = r1;
    }
}

// ---- decode: logits[e] = dot64(z[a], z[b]) ----------------------------------
__global__ void k_decode(const int* __restrict__ pos,
                         const int* __restrict__ neg,
                         float* __restrict__ out) {
    int gt = blockIdx.x * 256 + threadIdx.x;
    int e = gt >> 4;
    int j = gt & 15;
    int a, b;
    if (e < EP) { a = pos[e];        b = pos[EP + e]; }
    else        { int e2 = e - EP;  a = neg[e2];     b = neg[EN + e2]; }
    float4 za = __ldg((const float4*)(g_bufC + a * PAD) + j);
    float4 zb = __ldg((const float4*)(g_bufC + b * PAD) + j);
    float s = za.x * zb.x + za.y * zb.y + za.z * zb.z + za.w * zb.w;
#pragma unroll
    for (int o = 8; o; o >>= 1) s += __shfl_xor_sync(0xffffffffu, s, o);
    if (j == 0) out[e] = s;
}

// ---------------------------------------------------------------------------
extern "C" void kernel_launch(void* const* d_in, const int* in_sizes, int n_in,
                              void* d_out, int out_size) {
    const float* x   = (const float*)d_in[0];
    const int*   tr  = (const int*)d_in[1];
    const int*   pos = (const int*)d_in[2];
    const int*   neg = (const int*)d_in[3];
    const float* W1  = (const float*)d_in[4];
    const float* b1  = (const float*)d_in[5];
    const float* W2  = (const float*)d_in[6];
    const float* b2  = (const float*)d_in[7];
    float* out = (float*)d_out;

    const int* src = tr;
    const int* dst = tr + E_TRAIN;

    // CSR build (reused by both layers)
    k_zero<<<(N_NODES + 255) / 256, 256>>>();
    k_count<<<(E_TRAIN / 4 + 255) / 256, 256>>>(dst);
    k_scan<<<1, SCAN_T>>>();
    k_place<<<(E_TRAIN / 4 + 255) / 256, 256>>>(src, dst);

    // layer 1
    k_gemm1<<<N_NODES / 16, 256>>>(x, W1);
    k_agg<HID, true><<<N_NODES * 32 / 256, 256>>>(b1);

    // layer 2
    k_gemm2<<<N_NODES / 16, 256>>>(W2);
    k_agg<DOUT, false><<<N_NODES * 32 / 256, 256>>>(b2);

    // decode
    k_decode<<<(EP + EN) * 16 / 256, 256>>>(pos, neg, out);
}

// round 6
// speedup vs baseline: 1.2372x; 1.1517x over previous
#include <cuda_runtime.h>
#include <cuda_fp16.h>

// ---------------------------------------------------------------------------
// GCN link prediction, CSR-gather formulation:
//   hs = (x@W)*dinv (fp16) -> acc[c] = hs[c] + sum_{dst=c} hs[src]
//   out[c] = dinv[c]*acc[c] + b  (relu layer 1 -> fp32; layer 2 -> fp16 z)
// CSR build: count pass records per-edge rank (atomicAdd return); place pass
// is then atomic-free: esrc[rowptr[dst]+rank] = src.
// ---------------------------------------------------------------------------

#define N_NODES 50000
#define E_TRAIN 1600000
#define EP      200000
#define EN      200000
#define F_IN    50
#define HID     50
#define DOUT    64
#define PAD     64

__device__ __align__(256) __half g_bufA[N_NODES * PAD]; // hs fp16 (gather src)
__device__ __align__(256) float  g_bufC[N_NODES * PAD]; // layer-1 output (fp32)
__device__ __align__(256) __half g_z[N_NODES * PAD];    // layer-2 output (fp16)
__device__ int   g_deg[N_NODES];
__device__ int   g_rowptr[N_NODES + 1];
__device__ int   g_rank[E_TRAIN];
__device__ int   g_esrc[E_TRAIN];
__device__ float g_dinv[N_NODES];

// ---- degree + rank (8 edges/thread) -----------------------------------------
__global__ void k_zero() {
    int i = blockIdx.x * blockDim.x + threadIdx.x;
    if (i < N_NODES) g_deg[i] = 0;
}

__global__ void k_count(const int* __restrict__ dst) {
    int t = blockIdx.x * 256 + threadIdx.x;
    if (t < E_TRAIN / 8) {
        int4 d0 = __ldg((const int4*)dst + 2 * t);
        int4 d1 = __ldg((const int4*)dst + 2 * t + 1);
        int4 r0, r1;
        r0.x = atomicAdd(&g_deg[d0.x], 1);
        r0.y = atomicAdd(&g_deg[d0.y], 1);
        r0.z = atomicAdd(&g_deg[d0.z], 1);
        r0.w = atomicAdd(&g_deg[d0.w], 1);
        r1.x = atomicAdd(&g_deg[d1.x], 1);
        r1.y = atomicAdd(&g_deg[d1.y], 1);
        r1.z = atomicAdd(&g_deg[d1.z], 1);
        r1.w = atomicAdd(&g_deg[d1.w], 1);
        ((int4*)g_rank)[2 * t]     = r0;
        ((int4*)g_rank)[2 * t + 1] = r1;
    }
}

// ---- single-block exclusive scan -> rowptr/dinv -----------------------------
#define SCAN_T 1024
#define CHUNK  49     // 1024*49 = 50176 >= 50000

__global__ __launch_bounds__(SCAN_T) void k_scan() {
    __shared__ int part[SCAN_T];
    int t = threadIdx.x;
    int base = t * CHUNK;
    int s = 0;
#pragma unroll 7
    for (int i = 0; i < CHUNK; i++) {
        int idx = base + i;
        if (idx < N_NODES) s += __ldg(g_deg + idx);
    }
    part[t] = s;
    __syncthreads();
    for (int off = 1; off < SCAN_T; off <<= 1) {
        int v = (t >= off) ? part[t - off] : 0;
        __syncthreads();
        part[t] += v;
        __syncthreads();
    }
    int run = (t > 0) ? part[t - 1] : 0;
    for (int i = 0; i < CHUNK; i++) {
        int idx = base + i;
        if (idx < N_NODES) {
            int d = g_deg[idx];
            g_rowptr[idx] = run;
            g_dinv[idx]   = rsqrtf((float)(d + 1));   // +1 self loop
            run += d;
        }
    }
    if (t == SCAN_T - 1) g_rowptr[N_NODES] = run;
}

// ---- atomic-free placement (8 edges/thread) ---------------------------------
__global__ void k_place(const int* __restrict__ src, const int* __restrict__ dst) {
    int t = blockIdx.x * 256 + threadIdx.x;
    if (t < E_TRAIN / 8) {
        int4 s0 = __ldg((const int4*)src + 2 * t);
        int4 s1 = __ldg((const int4*)src + 2 * t + 1);
        int4 d0 = __ldg((const int4*)dst + 2 * t);
        int4 d1 = __ldg((const int4*)dst + 2 * t + 1);
        int4 r0 = __ldg((const int4*)g_rank + 2 * t);
        int4 r1 = __ldg((const int4*)g_rank + 2 * t + 1);
        g_esrc[__ldg(g_rowptr + d0.x) + r0.x] = s0.x;
        g_esrc[__ldg(g_rowptr + d0.y) + r0.y] = s0.y;
        g_esrc[__ldg(g_rowptr + d0.z) + r0.z] = s0.z;
        g_esrc[__ldg(g_rowptr + d0.w) + r0.w] = s0.w;
        g_esrc[__ldg(g_rowptr + d1.x) + r1.x] = s1.x;
        g_esrc[__ldg(g_rowptr + d1.y) + r1.y] = s1.y;
        g_esrc[__ldg(g_rowptr + d1.z) + r1.z] = s1.z;
        g_esrc[__ldg(g_rowptr + d1.w) + r1.w] = s1.w;
    }
}

// ---- GEMM 1: bufA = fp16( dinv[i] * (x @ W1) ), W padded to 64 cols --------
__global__ __launch_bounds__(256) void k_gemm1(const float* __restrict__ x,
                                               const float* __restrict__ W1) {
    __shared__ float ws[F_IN][64];
    __shared__ float xs[16][F_IN + 2];
    int tid = threadIdx.x;
    int nodeBase = blockIdx.x * 16;                 // 3125 blocks, always full
    for (int t = tid; t < F_IN * 64; t += 256) {
        int k = t >> 6, j = t & 63;
        ws[k][j] = (j < HID) ? W1[k * HID + j] : 0.f;
    }
    for (int t = tid; t < 16 * F_IN; t += 256) {
        int n = t / F_IN, k = t % F_IN;
        xs[n][k] = x[(nodeBase + n) * F_IN + k];
    }
    __syncthreads();
    int n = tid >> 4, jq = tid & 15;
    int node = nodeBase + n;
    float4 acc = make_float4(0.f, 0.f, 0.f, 0.f);
#pragma unroll
    for (int k = 0; k < F_IN; k++) {
        float xv = xs[n][k];
        float4 w = *(const float4*)&ws[k][jq * 4];
        acc.x = fmaf(xv, w.x, acc.x);
        acc.y = fmaf(xv, w.y, acc.y);
        acc.z = fmaf(xv, w.z, acc.z);
        acc.w = fmaf(xv, w.w, acc.w);
    }
    float di = g_dinv[node];
    __half2 p0 = __floats2half2_rn(acc.x * di, acc.y * di);
    __half2 p1 = __floats2half2_rn(acc.z * di, acc.w * di);
    uint2 st;
    st.x = *(unsigned*)&p0;
    st.y = *(unsigned*)&p1;
    *(uint2*)&g_bufA[node * PAD + jq * 4] = st;
}

// ---- GEMM 2: bufA = fp16( dinv[i] * (bufC @ W2) ) ---------------------------
__global__ __launch_bounds__(256) void k_gemm2(const float* __restrict__ W2) {
    __shared__ float ws[HID][64];
    __shared__ float xs[16][HID + 2];
    int tid = threadIdx.x;
    int nodeBase = blockIdx.x * 16;
    for (int t = tid; t < HID * 64; t += 256) {
        int k = t >> 6, j = t & 63;
        ws[k][j] = W2[k * DOUT + j];
    }
    for (int t = tid; t < 16 * HID; t += 256) {
        int n = t / HID, k = t % HID;
        xs[n][k] = g_bufC[(nodeBase + n) * PAD + k];
    }
    __syncthreads();
    int n = tid >> 4, jq = tid & 15;
    int node = nodeBase + n;
    float4 acc = make_float4(0.f, 0.f, 0.f, 0.f);
#pragma unroll
    for (int k = 0; k < HID; k++) {
        float xv = xs[n][k];
        float4 w = *(const float4*)&ws[k][jq * 4];
        acc.x = fmaf(xv, w.x, acc.x);
        acc.y = fmaf(xv, w.y, acc.y);
        acc.z = fmaf(xv, w.z, acc.z);
        acc.w = fmaf(xv, w.w, acc.w);
    }
    float di = g_dinv[node];
    __half2 p0 = __floats2half2_rn(acc.x * di, acc.y * di);
    __half2 p1 = __floats2half2_rn(acc.z * di, acc.w * di);
    uint2 st;
    st.x = *(unsigned*)&p0;
    st.y = *(unsigned*)&p1;
    *(uint2*)&g_bufA[node * PAD + jq * 4] = st;
}

// ---- CSR aggregation + fused epilogue ---------------------------------------
// One warp per node. 4 edge-groups of 8 lanes; lane q owns 16B chunk q
// (8 halves). CH = active chunks (7 for layer 1: 50 cols). Unroll 4.
// FINAL=false: fp32 store to g_bufC (+relu). FINAL=true: fp16 store to g_z.
template <int CH, int NB, bool RELU, bool FINAL>
__global__ __launch_bounds__(256) void k_agg(const float* __restrict__ bias) {
    int node = (blockIdx.x * 256 + threadIdx.x) >> 5;   // 6250 blocks exact
    int lane = threadIdx.x & 31;
    int g = lane >> 3, q = lane & 7;
    int rp = g_rowptr[node], re = g_rowptr[node + 1];
    float a0 = 0.f, a1 = 0.f, a2 = 0.f, a3 = 0.f;
    float a4 = 0.f, a5 = 0.f, a6 = 0.f, a7 = 0.f;
    const uint4* rows = (const uint4*)g_bufA;           // 8 uint4 per row
    const bool act = (CH == 8) || (q < CH);

#define ACCUM(U) do {                                                   \
        __half2* hp = (__half2*)&(U);                                   \
        float2 f0 = __half22float2(hp[0]);                              \
        float2 f1 = __half22float2(hp[1]);                              \
        float2 f2 = __half22float2(hp[2]);                              \
        float2 f3 = __half22float2(hp[3]);                              \
        a0 += f0.x; a1 += f0.y; a2 += f1.x; a3 += f1.y;                 \
        a4 += f2.x; a5 += f2.y; a6 += f3.x; a7 += f3.y;                 \
    } while (0)

    if (g == 0 && act) {                                // self loop
        uint4 u = __ldg(rows + node * 8 + q);
        ACCUM(u);
    }
    int e = rp + g;
    for (; e + 12 < re; e += 16) {
        int s0 = __ldg(g_esrc + e);
        int s1 = __ldg(g_esrc + e + 4);
        int s2 = __ldg(g_esrc + e + 8);
        int s3 = __ldg(g_esrc + e + 12);
        if (act) {
            uint4 u0 = __ldg(rows + s0 * 8 + q);
            uint4 u1 = __ldg(rows + s1 * 8 + q);
            uint4 u2 = __ldg(rows + s2 * 8 + q);
            uint4 u3 = __ldg(rows + s3 * 8 + q);
            ACCUM(u0); ACCUM(u1); ACCUM(u2); ACCUM(u3);
        }
    }
    for (; e + 4 < re; e += 8) {
        int s0 = __ldg(g_esrc + e);
        int s1 = __ldg(g_esrc + e + 4);
        if (act) {
            uint4 u0 = __ldg(rows + s0 * 8 + q);
            uint4 u1 = __ldg(rows + s1 * 8 + q);
            ACCUM(u0); ACCUM(u1);
        }
    }
    if (e < re) {
        int s0 = __ldg(g_esrc + e);
        if (act) {
            uint4 u0 = __ldg(rows + s0 * 8 + q);
            ACCUM(u0);
        }
    }
#undef ACCUM

#define RED(off) do {                                                   \
        a0 += __shfl_xor_sync(0xffffffffu, a0, off);                    \
        a1 += __shfl_xor_sync(0xffffffffu, a1, off);                    \
        a2 += __shfl_xor_sync(0xffffffffu, a2, off);                    \
        a3 += __shfl_xor_sync(0xffffffffu, a3, off);                    \
        a4 += __shfl_xor_sync(0xffffffffu, a4, off);                    \
        a5 += __shfl_xor_sync(0xffffffffu, a5, off);                    \
        a6 += __shfl_xor_sync(0xffffffffu, a6, off);                    \
        a7 += __shfl_xor_sync(0xffffffffu, a7, off);                    \
    } while (0)
    RED(8);
    RED(16);
#undef RED

    if (g == 0 && act) {
        float di = g_dinv[node];
        int j0 = q * 8;
        float acc[8] = {a0, a1, a2, a3, a4, a5, a6, a7};
        float v[8];
#pragma unroll
        for (int i = 0; i < 8; i++) {
            int j = j0 + i;
            float bv = (j < NB) ? __ldg(bias + j) : 0.f;
            float r = fmaf(di, acc[i], bv);
            if (RELU) r = fmaxf(r, 0.f);
            v[i] = r;
        }
        if (FINAL) {
            __half2 h0 = __floats2half2_rn(v[0], v[1]);
            __half2 h1 = __floats2half2_rn(v[2], v[3]);
            __half2 h2 = __floats2half2_rn(v[4], v[5]);
            __half2 h3 = __floats2half2_rn(v[6], v[7]);
            uint4 st;
            st.x = *(unsigned*)&h0; st.y = *(unsigned*)&h1;
            st.z = *(unsigned*)&h2; st.w = *(unsigned*)&h3;
            *(uint4*)&g_z[node * PAD + j0] = st;
        } else {
            float4 r0 = make_float4(v[0], v[1], v[2], v[3]);
            float4 r1 = make_float4(v[4], v[5], v[6], v[7]);
            *(float4*)(g_bufC + node * PAD + j0)     = r0;
            *(float4*)(g_bufC + node * PAD + j0 + 4) = r1;
        }
    }
}

// ---- decode: logits[e] = dot64(z[a], z[b]), z fp16 --------------------------
__global__ void k_decode(const int* __restrict__ pos,
                         const int* __restrict__ neg,
                         float* __restrict__ out) {
    int gt = blockIdx.x * 256 + threadIdx.x;   // 12500 blocks exact
    int e = gt >> 3;
    int j = gt & 7;
    int a, b;
    if (e < EP) { a = pos[e];        b = pos[EP + e]; }
    else        { int e2 = e - EP;  a = neg[e2];     b = neg[EN + e2]; }
    uint4 ua = __ldg((const uint4*)(g_z + a * PAD) + j);
    uint4 ub = __ldg((const uint4*)(g_z + b * PAD) + j);
    __half2* ha = (__half2*)&ua;
    __half2* hb = (__half2*)&ub;
    float s = 0.f;
#pragma unroll
    for (int i = 0; i < 4; i++) {
        float2 fa = __half22float2(ha[i]);
        float2 fb = __half22float2(hb[i]);
        s = fmaf(fa.x, fb.x, s);
        s = fmaf(fa.y, fb.y, s);
    }
#pragma unroll
    for (int o = 4; o; o >>= 1) s += __shfl_xor_sync(0xffffffffu, s, o);
    if (j == 0) out[e] = s;
}

// ---------------------------------------------------------------------------
extern "C" void kernel_launch(void* const* d_in, const int* in_sizes, int n_in,
                              void* d_out, int out_size) {
    const float* x   = (const float*)d_in[0];
    const int*   tr  = (const int*)d_in[1];
    const int*   pos = (const int*)d_in[2];
    const int*   neg = (const int*)d_in[3];
    const float* W1  = (const float*)d_in[4];
    const float* b1  = (const float*)d_in[5];
    const float* W2  = (const float*)d_in[6];
    const float* b2  = (const float*)d_in[7];
    float* out = (float*)d_out;

    const int* src = tr;
    const int* dst = tr + E_TRAIN;

    // CSR build
    k_zero<<<(N_NODES + 255) / 256, 256>>>();
    k_count<<<(E_TRAIN / 8 + 255) / 256, 256>>>(dst);
    k_scan<<<1, SCAN_T>>>();
    k_place<<<(E_TRAIN / 8 + 255) / 256, 256>>>(src, dst);

    // layer 1
    k_gemm1<<<N_NODES / 16, 256>>>(x, W1);
    k_agg<7, HID, true, false><<<N_NODES * 32 / 256, 256>>>(b1);

    // layer 2
    k_gemm2<<<N_NODES / 16, 256>>>(W2);
    k_agg<8, DOUT, false, true><<<N_NODES * 32 / 256, 256>>>(b2);

    // decode
    k_decode<<<(EP + EN) * 8 / 256, 256>>>(pos, neg, out);
}